// round 2
// baseline (speedup 1.0000x reference)
#include <cuda_runtime.h>
#include <cuda_bf16.h>

#define BINS 256
#define NWARPS 8            // blockDim = 256 -> 8 warps, one smem histogram copy per warp
#define HIST_BLOCKS 2048
#define HIST_THREADS 256

// Scratch: global int histogram (device global array -> no allocation)
__device__ unsigned int g_hist[BINS];

__global__ void zero_hist_kernel() {
    g_hist[threadIdx.x] = 0u;
}

__device__ __forceinline__ void bin_one(float x, unsigned int* warp_hist) {
    // torch.histc: bins over [LO,HI]=[-4,4]; x==HI -> last bin; outside ignored.
    if (x >= -4.0f && x <= 4.0f) {
        float t = (x - (-4.0f)) * 32.0f;
        int idx = (int)floorf(t);
        idx = min(idx, BINS - 1);
        atomicAdd(&warp_hist[idx], 1u);
    }
}

__global__ void __launch_bounds__(HIST_THREADS, 8)
hist_kernel(const float* __restrict__ x, long long n) {
    __shared__ unsigned int sh[NWARPS][BINS];
    const int tid  = threadIdx.x;
    const int warp = tid >> 5;
    unsigned int* wh = sh[warp];

    // Zero shared histograms
    #pragma unroll
    for (int i = tid; i < NWARPS * BINS; i += HIST_THREADS)
        ((unsigned int*)sh)[i] = 0u;
    __syncthreads();

    // Vectorized main loop: float4 grid-stride
    const long long n4 = n >> 2;
    const float4* __restrict__ x4 = (const float4*)x;
    const long long stride = (long long)gridDim.x * HIST_THREADS;
    for (long long i = (long long)blockIdx.x * HIST_THREADS + tid; i < n4; i += stride) {
        float4 v = x4[i];
        bin_one(v.x, wh);
        bin_one(v.y, wh);
        bin_one(v.z, wh);
        bin_one(v.w, wh);
    }

    // Scalar tail (n not multiple of 4) — handled by block 0 only
    if (blockIdx.x == 0) {
        for (long long i = (n4 << 2) + tid; i < n; i += HIST_THREADS)
            bin_one(x[i], wh);
    }
    __syncthreads();

    // Reduce per-warp copies, one gmem atomic per bin per block
    for (int b = tid; b < BINS; b += HIST_THREADS) {
        unsigned int s = 0;
        #pragma unroll
        for (int c = 0; c < NWARPS; c++) s += sh[c][b];
        if (s) atomicAdd(&g_hist[b], s);
    }
}

// Reference returns (h, h): write the histogram into EVERY 256-element chunk
// of the output buffer (out_size = 2*BINS for the two outputs).
__global__ void finalize_kernel(float* __restrict__ out, int out_size) {
    float v = (float)g_hist[threadIdx.x];
    for (int base = 0; base + (int)threadIdx.x < out_size; base += BINS)
        out[base + threadIdx.x] = v;
}

extern "C" void kernel_launch(void* const* d_in, const int* in_sizes, int n_in,
                              void* d_out, int out_size) {
    const float* x = (const float*)d_in[0];
    long long n = (long long)in_sizes[0];
    float* out = (float*)d_out;

    zero_hist_kernel<<<1, BINS>>>();
    hist_kernel<<<HIST_BLOCKS, HIST_THREADS>>>(x, n);
    finalize_kernel<<<1, BINS>>>(out, out_size);
}

// round 3
// speedup vs baseline: 1.1030x; 1.1030x over previous
#include <cuda_runtime.h>
#include <cuda_bf16.h>

#define BINS 256
#define NWARPS 8            // blockDim = 256 -> 8 warps, one smem histogram copy per warp
#define HIST_BLOCKS 1184    // 148 SMs x 8 blocks -> exactly one wave at occupancy 8
#define HIST_THREADS 256

// Scratch: global int histogram (device global array -> no allocation).
// Zero-initialized at module load; finalize_kernel resets it to 0 every launch,
// so every graph replay starts from zero. No separate zeroing kernel needed.
__device__ unsigned int g_hist[BINS];

__device__ __forceinline__ void bin_one(float x, unsigned int* warp_hist) {
    // torch.histc: bins over [LO,HI]=[-4,4]; x==HI -> last bin; outside ignored.
    if (x >= -4.0f && x <= 4.0f) {
        float t = (x - (-4.0f)) * 32.0f;   // add-then-mul, matches reference rounding
        int idx = (int)floorf(t);
        idx = min(idx, BINS - 1);
        atomicAdd(&warp_hist[idx], 1u);
    }
}

__device__ __forceinline__ void bin4(float4 v, unsigned int* wh) {
    bin_one(v.x, wh);
    bin_one(v.y, wh);
    bin_one(v.z, wh);
    bin_one(v.w, wh);
}

__global__ void __launch_bounds__(HIST_THREADS, 8)
hist_kernel(const float* __restrict__ x, long long n) {
    __shared__ unsigned int sh[NWARPS][BINS];
    const int tid  = threadIdx.x;
    const int warp = tid >> 5;
    unsigned int* wh = sh[warp];

    // Zero shared histograms
    #pragma unroll
    for (int i = tid; i < NWARPS * BINS; i += HIST_THREADS)
        ((unsigned int*)sh)[i] = 0u;
    __syncthreads();

    const long long n4 = n >> 2;
    const float4* __restrict__ x4 = (const float4*)x;
    const long long stride = (long long)gridDim.x * HIST_THREADS;
    long long i = (long long)blockIdx.x * HIST_THREADS + tid;

    // Main loop: 4 independent LDG.128 front-batched per iteration (MLP_p1 = 4)
    for (; i + 3 * stride < n4; i += 4 * stride) {
        float4 a = x4[i];
        float4 b = x4[i + stride];
        float4 c = x4[i + 2 * stride];
        float4 d = x4[i + 3 * stride];
        bin4(a, wh);
        bin4(b, wh);
        bin4(c, wh);
        bin4(d, wh);
    }
    // Remainder float4s
    for (; i < n4; i += stride)
        bin4(x4[i], wh);

    // Scalar tail (n not multiple of 4) — block 0 only
    if (blockIdx.x == 0) {
        for (long long j = (n4 << 2) + tid; j < n; j += HIST_THREADS)
            bin_one(x[j], wh);
    }
    __syncthreads();

    // Reduce per-warp copies, one gmem atomic per bin per block
    for (int b = tid; b < BINS; b += HIST_THREADS) {
        unsigned int s = 0;
        #pragma unroll
        for (int c = 0; c < NWARPS; c++) s += sh[c][b];
        if (s) atomicAdd(&g_hist[b], s);
    }
}

// Reference returns (h, h): write the histogram into EVERY 256-element chunk
// of the output buffer, then reset g_hist for the next replay.
__global__ void finalize_kernel(float* __restrict__ out, int out_size) {
    const int t = threadIdx.x;
    unsigned int v = g_hist[t];
    g_hist[t] = 0u;                      // reset for next graph replay
    float f = (float)v;
    for (int base = 0; base + t < out_size; base += BINS)
        out[base + t] = f;
}

extern "C" void kernel_launch(void* const* d_in, const int* in_sizes, int n_in,
                              void* d_out, int out_size) {
    const float* x = (const float*)d_in[0];
    long long n = (long long)in_sizes[0];
    float* out = (float*)d_out;

    hist_kernel<<<HIST_BLOCKS, HIST_THREADS>>>(x, n);
    finalize_kernel<<<1, BINS>>>(out, out_size);
}